// round 2
// baseline (speedup 1.0000x reference)
#include <cuda_runtime.h>
#include <math.h>

// Problem constants (match reference)
#define Wd 96
#define Hd 96
#define Dd 64
#define Ad 90
#define Ud 96
#define Vd 64
#define NSTEPS 194          // H + W + 2
#define NRAYS  (Ad * Ud)    // 8640
#define RPB    4            // rays per block in accumulate kernel

// Static device scratch (no allocations allowed).
// Packed trace: .x = voxel base offset (i*H*D + j*D), .y = weight bits.
__device__ int2 g_trace[NRAYS * NSTEPS];
__device__ int  g_cnt[NRAYS];

__device__ __forceinline__ void t_for(float p0, float dp, float pmin, float pmax,
                                      float& lo, float& hi) {
    const float EPS = 1e-12f;
    bool par = fabsf(dp) < EPS;
    float safe = par ? 1.0f : dp;
    float t0 = (pmin - p0) / safe;
    float t1 = (pmax - p0) / safe;
    lo = fminf(t0, t1);
    hi = fmaxf(t0, t1);
    bool inside = (p0 >= pmin) && (p0 <= pmax);
    if (par) {
        lo = inside ? -INFINITY : INFINITY;
        hi = inside ?  INFINITY : -INFINITY;
    }
}

// One thread per ray: replicate the reference float32 Siddon scan exactly,
// compacting nonzero (offset, weight) steps.
__global__ void siddon_trace_kernel() {
    int r = blockIdx.x * blockDim.x + threadIdx.x;
    if (r >= NRAYS) return;

    const float EPS  = 1e-12f;
    const float DIAG = 1.41421356237309515f;  // f32(sqrt(2))

    int a  = r / Ud;
    int ui = r % Ud;

    // angles = linspace(0, pi, 90, endpoint=False) in f32
    const float ang_step = 3.14159274101257324f / 90.0f;
    float ang = (float)a * ang_step;
    float ct = (float)cos((double)ang);
    float st = (float)sin((double)ang);

    float u  = (float)ui - 47.5f;          // (U-1)/2 = 47.5, SU=1
    float dx = ct, dy = st;
    float x0 = -u * st;
    float y0 =  u * ct;

    const float pmin = -47.5f, pmax = 47.5f;   // symmetric W==H extents

    float tx0, tx1, ty0, ty1;
    t_for(x0, dx, pmin, pmax, tx0, tx1);
    t_for(y0, dy, pmin, pmax, ty0, ty1);

    float t_entry = fmaxf(tx0, ty0);
    float t_exit  = fminf(tx1, ty1);
    bool  alive   = t_entry < t_exit;
    float te  = alive ? t_entry : 0.0f;
    float tex = alive ? t_exit  : 0.0f;

    float xe = x0 + te * dx;
    float ye = y0 + te * dy;

    // jnp.round == rintf (round half to even)
    int i = (int)fminf(fmaxf(rintf(xe + 47.5f), 0.0f), (float)(Wd - 1));
    int j = (int)fminf(fmaxf(rintf(ye + 47.5f), 0.0f), (float)(Hd - 1));

    float x = xe, y = ye, t = te;
    float denom = fmaxf(fabsf(dx) + fabsf(dy), EPS);

    bool okx = fabsf(dx) > EPS;
    bool oky = fabsf(dy) > EPS;

    int cnt  = 0;
    int base = r * NSTEPS;

    for (int s = 0; s < NSTEPS; s++) {
        if (!alive) break;
        bool valid = alive && (t < tex - EPS);

        float fi = (float)i, fj = (float)j;
        float xn = (dx > 0.0f) ? ((fi + 0.5f) - 47.5f)
                               : ((dx < 0.0f) ? ((fi - 0.5f) - 47.5f) : INFINITY);
        float yn = (dy > 0.0f) ? ((fj + 0.5f) - 47.5f)
                               : ((dy < 0.0f) ? ((fj - 0.5f) - 47.5f) : INFINITY);

        float tx = okx ? (xn - x) / dx : INFINITY;
        float ty = oky ? (yn - y) / dy : INFINITY;

        float dt  = fminf(fminf(tx, ty), tex - t);
        float seg = fmaxf(0.0f, dt * DIAG / denom);
        float w   = valid ? seg : 0.0f;

        if (w > 0.0f) {
            int2 e;
            e.x = i * (Hd * Dd) + j * Dd;
            e.y = __float_as_int(w);
            g_trace[base + cnt] = e;
            cnt++;
        }

        int i_n = i + ((tx <= ty) ? ((dx > 0.0f) ? 1 : -1) : 0);
        int j_n = j + ((ty <= tx) ? ((dy > 0.0f) ? 1 : -1) : 0);
        bool inb = (i_n >= 0) && (i_n < Wd) && (j_n >= 0) && (j_n < Hd);

        float dts = valid ? dt : 0.0f;
        if (valid) { i = i_n; j = j_n; }
        x += dx * dts;
        y += dy * dts;
        t += dts;
        alive = valid && inb;
    }
    g_cnt[r] = cnt;
}

// Block = RPB rays x 64 depth lanes. Stage the ray trace in smem, then
// each lane v accumulates sum_n vol[off_n + v] * w_n.
__global__ void siddon_accum_kernel(const float* __restrict__ vol,
                                    float* __restrict__ out) {
    __shared__ int2 s_t[RPB][NSTEPS];

    int yy  = threadIdx.y;       // ray within block
    int v   = threadIdx.x;       // depth lane (0..63)
    int ray = blockIdx.x * RPB + yy;

    int cnt  = g_cnt[ray];
    int base = ray * NSTEPS;

    for (int n = v; n < cnt; n += Vd)
        s_t[yy][n] = g_trace[base + n];
    __syncthreads();

    const float* volp = vol + v;
    float acc0 = 0.0f, acc1 = 0.0f, acc2 = 0.0f, acc3 = 0.0f;

    int n = 0;
    for (; n + 3 < cnt; n += 4) {
        int2 e0 = s_t[yy][n + 0];
        int2 e1 = s_t[yy][n + 1];
        int2 e2 = s_t[yy][n + 2];
        int2 e3 = s_t[yy][n + 3];
        acc0 += volp[e0.x] * __int_as_float(e0.y);
        acc1 += volp[e1.x] * __int_as_float(e1.y);
        acc2 += volp[e2.x] * __int_as_float(e2.y);
        acc3 += volp[e3.x] * __int_as_float(e3.y);
    }
    for (; n < cnt; n++) {
        int2 e = s_t[yy][n];
        acc0 += volp[e.x] * __int_as_float(e.y);
    }

    int a  = ray / Ud;
    int ui = ray % Ud;
    // output layout (B,C,U,A,V): idx = u*(A*V) + a*V + v
    out[(ui * Ad + a) * Vd + v] = (acc0 + acc1) + (acc2 + acc3);
}

extern "C" void kernel_launch(void* const* d_in, const int* in_sizes, int n_in,
                              void* d_out, int out_size) {
    const float* vol = (const float*)d_in[0];
    float* out = (float*)d_out;

    siddon_trace_kernel<<<(NRAYS + 255) / 256, 256>>>();

    dim3 blk(Vd, RPB);                 // 64 x 4 = 256 threads
    dim3 grd(NRAYS / RPB);             // 2160 blocks
    siddon_accum_kernel<<<grd, blk>>>(vol, out);
}

// round 3
// speedup vs baseline: 1.8606x; 1.8606x over previous
#include <cuda_runtime.h>
#include <math.h>

// Problem constants (match reference)
#define Wd 96
#define Hd 96
#define Dd 64
#define Ad 90
#define Ud 96
#define Vd 64
#define NSTEPS 194          // H + W + 2
#define NRAYS  (Ad * Ud)    // 8640
#define RPB    4            // rays per block in accumulate kernel

// Static device scratch (no allocations allowed).
// Packed trace: .x = voxel base offset (i*H*D + j*D), .y = weight bits.
__device__ int2 g_trace[NRAYS * NSTEPS];
__device__ int  g_cnt[NRAYS];

__device__ __forceinline__ void t_for(float p0, float dp, float pmin, float pmax,
                                      float& lo, float& hi) {
    const float EPS = 1e-12f;
    bool par = fabsf(dp) < EPS;
    float safe = par ? 1.0f : dp;
    float t0 = (pmin - p0) / safe;
    float t1 = (pmax - p0) / safe;
    lo = fminf(t0, t1);
    hi = fmaxf(t0, t1);
    bool inside = (p0 >= pmin) && (p0 <= pmax);
    if (par) {
        lo = inside ? -INFINITY : INFINITY;
        hi = inside ?  INFINITY : -INFINITY;
    }
}

// One thread per ray. 64-thread blocks -> 135 blocks -> all SMs covered.
// Per-step divisions replaced by multiply with per-ray reciprocals.
__global__ __launch_bounds__(64) void siddon_trace_kernel() {
    int r = blockIdx.x * blockDim.x + threadIdx.x;
    if (r >= NRAYS) return;

    const float EPS  = 1e-12f;
    const float DIAG = 1.41421356237309515f;  // f32(sqrt(2))

    int a  = r / Ud;
    int ui = r % Ud;

    // angles = linspace(0, pi, 90, endpoint=False) in f32
    const float ang_step = 3.14159274101257324f / 90.0f;
    float ang = (float)a * ang_step;
    float ct = (float)cos((double)ang);
    float st = (float)sin((double)ang);

    float u  = (float)ui - 47.5f;          // (U-1)/2 = 47.5, SU=1
    float dx = ct, dy = st;
    float x0 = -u * st;
    float y0 =  u * ct;

    const float pmin = -47.5f, pmax = 47.5f;   // symmetric W==H extents

    float tx0, tx1, ty0, ty1;
    t_for(x0, dx, pmin, pmax, tx0, tx1);
    t_for(y0, dy, pmin, pmax, ty0, ty1);

    float t_entry = fmaxf(tx0, ty0);
    float t_exit  = fminf(tx1, ty1);
    bool  alive   = t_entry < t_exit;
    float te  = alive ? t_entry : 0.0f;
    float tex = alive ? t_exit  : 0.0f;

    float xe = x0 + te * dx;
    float ye = y0 + te * dy;

    // jnp.round == rintf (round half to even)
    int i = (int)fminf(fmaxf(rintf(xe + 47.5f), 0.0f), (float)(Wd - 1));
    int j = (int)fminf(fmaxf(rintf(ye + 47.5f), 0.0f), (float)(Hd - 1));

    float x = xe, y = ye, t = te;
    float inv_denom = 1.0f / fmaxf(fabsf(dx) + fabsf(dy), EPS);
    float wscale = DIAG * inv_denom;

    bool okx = fabsf(dx) > EPS;
    bool oky = fabsf(dy) > EPS;
    float inv_dx = okx ? (1.0f / dx) : 0.0f;
    float inv_dy = oky ? (1.0f / dy) : 0.0f;

    // step direction / half-cell offsets (constants per ray)
    float xoff = (dx > 0.0f) ? (0.5f - 47.5f) : (-0.5f - 47.5f);
    float yoff = (dy > 0.0f) ? (0.5f - 47.5f) : (-0.5f - 47.5f);
    int   istep = (dx > 0.0f) ? 1 : -1;
    int   jstep = (dy > 0.0f) ? 1 : -1;

    int cnt  = 0;
    int base = r * NSTEPS;

    for (int s = 0; s < NSTEPS; s++) {
        if (!alive) break;
        bool valid = (t < tex - EPS);

        float tx = okx ? (((float)i + xoff) - x) * inv_dx : INFINITY;
        float ty = oky ? (((float)j + yoff) - y) * inv_dy : INFINITY;

        float dt = fminf(fminf(tx, ty), tex - t);
        float w  = fmaxf(0.0f, dt * wscale);

        if (valid && w > 0.0f) {
            int2 e;
            e.x = i * (Hd * Dd) + j * Dd;
            e.y = __float_as_int(w);
            g_trace[base + cnt] = e;
            cnt++;
        }

        int i_n = i + ((tx <= ty) ? istep : 0);
        int j_n = j + ((ty <= tx) ? jstep : 0);
        bool inb = (i_n >= 0) && (i_n < Wd) && (j_n >= 0) && (j_n < Hd);

        if (valid) {
            i = i_n; j = j_n;
            x += dx * dt;
            y += dy * dt;
            t += dt;
        }
        alive = valid && inb;
    }
    g_cnt[r] = cnt;
}

// Block = RPB rays x 32 lanes; each lane handles 2 v-values via float2.
// One warp == one ray: no block-wide barrier needed.
__global__ __launch_bounds__(32 * RPB) void siddon_accum_kernel(
        const float* __restrict__ vol, float* __restrict__ out) {
    __shared__ int2 s_t[RPB][NSTEPS];

    int yy  = threadIdx.y;       // ray within block (== warp id)
    int x   = threadIdx.x;       // lane: covers v = 2x, 2x+1
    int ray = blockIdx.x * RPB + yy;

    int cnt  = g_cnt[ray];       // uniform per warp -> broadcast load
    int base = ray * NSTEPS;

    for (int n = x; n < cnt; n += 32)
        s_t[yy][n] = g_trace[base + n];
    __syncwarp();

    const float2* vp = (const float2*)vol;
    float a0x = 0.0f, a0y = 0.0f, a1x = 0.0f, a1y = 0.0f;

    int n = 0;
    for (; n + 1 < cnt; n += 2) {
        int2 e0 = s_t[yy][n + 0];
        int2 e1 = s_t[yy][n + 1];
        float2 v0 = vp[(e0.x >> 1) + x];
        float2 v1 = vp[(e1.x >> 1) + x];
        float  w0 = __int_as_float(e0.y);
        float  w1 = __int_as_float(e1.y);
        a0x += v0.x * w0;  a0y += v0.y * w0;
        a1x += v1.x * w1;  a1y += v1.y * w1;
    }
    if (n < cnt) {
        int2 e = s_t[yy][n];
        float2 v = vp[(e.x >> 1) + x];
        float  w = __int_as_float(e.y);
        a0x += v.x * w;  a0y += v.y * w;
    }

    int a  = ray / Ud;
    int ui = ray % Ud;
    // output layout (B,C,U,A,V): float2 index = (u*A + a)*32 + x
    float2 res;
    res.x = a0x + a1x;
    res.y = a0y + a1y;
    ((float2*)out)[(ui * Ad + a) * 32 + x] = res;
}

extern "C" void kernel_launch(void* const* d_in, const int* in_sizes, int n_in,
                              void* d_out, int out_size) {
    const float* vol = (const float*)d_in[0];
    float* out = (float*)d_out;

    siddon_trace_kernel<<<(NRAYS + 63) / 64, 64>>>();

    dim3 blk(32, RPB);                 // 128 threads
    dim3 grd(NRAYS / RPB);             // 2160 blocks
    siddon_accum_kernel<<<grd, blk>>>(vol, out);
}